// round 2
// baseline (speedup 1.0000x reference)
#include <cuda_runtime.h>

// Problem constants (fixed shapes per reference)
#define NN    50000
#define EE    800000
#define TOT   (EE + NN)      // edges + self loops
#define HEADS 12
#define OC    32
#define ICC   128
#define HC    (HEADS * OC)   // 384
#define NEG_SLOPE 0.2f

// ---------------- scratch (device globals; no allocations allowed) ----------
__device__ float    g_h[(size_t)NN * HC];        // 76.8 MB  h = x@W
__device__ float    g_asrc[NN * HEADS];          // 2.4 MB
__device__ float    g_adst[NN * HEADS];          // 2.4 MB
__device__ unsigned g_m[NN * HEADS];             // segment max (ordered-uint floats)
__device__ float    g_denom[NN * HEADS];         // softmax denominators
__device__ float    g_ex[(size_t)TOT * HEADS];   // 40.8 MB  exp(e - m[dst])
__device__ float    g_y[NN * OC];                // head-sum accumulator
__device__ int      g_is64;                      // edge_index dtype flag

// ordered-uint encoding of float: monotone increasing, works with atomicMax(unsigned)
__device__ __forceinline__ unsigned f2ord(float f) {
    unsigned u = __float_as_uint(f);
    return (u & 0x80000000u) ? ~u : (u | 0x80000000u);
}
__device__ __forceinline__ float ord2f(unsigned u) {
    return __uint_as_float((u & 0x80000000u) ? (u ^ 0x80000000u) : ~u);
}

// Load edge e's (src, dst), robust to int32 vs int64 edge_index.
__device__ __forceinline__ void load_edge(const void* __restrict__ ei, int e,
                                          int& src, int& dst) {
    if (e >= EE) { src = dst = e - EE; return; }   // self-loop
    if (g_is64) {
        const long long* p = (const long long*)ei;
        src = (int)p[e];
        dst = (int)p[EE + e];
    } else {
        const int* p = (const int*)ei;
        src = p[e];
        dst = p[EE + e];
    }
}

// ---------------- K-1: detect edge_index dtype ------------------------------
__global__ void k_detect(const int* __restrict__ ei32) {
    if (threadIdx.x == 0 && blockIdx.x == 0) {
        bool hi_all_zero = true;
        for (int i = 0; i < 32; i++)
            if (ei32[2 * i + 1] != 0) hi_all_zero = false;
        g_is64 = hi_all_zero ? 1 : 0;
    }
}

// ---------------- K0: init accumulators ------------------------------------
__global__ void k_init() {
    int i = blockIdx.x * blockDim.x + threadIdx.x;
    if (i < NN * OC) g_y[i] = 0.f;
    if (i < NN * HEADS) {
        g_m[i] = 0x007FFFFFu;   // f2ord(-inf)
        g_denom[i] = 0.f;
    }
}

// ---------------- K1: h = x @ W  (50000x128 @ 128x384) ---------------------
#define BM 64
#define BN 64
#define BK 32
__global__ void k_gemm(const float* __restrict__ x, const float* __restrict__ W) {
    __shared__ float As[BK][BM + 1];
    __shared__ float Bs[BK][BN];
    int bx = blockIdx.x;               // 0..5   (384/64)
    int by = blockIdx.y;               // node tile
    int tid = threadIdx.x;             // 256
    int tx = tid % 16, ty = tid / 16;
    int row0 = by * BM, col0 = bx * BN;

    float acc[4][4];
#pragma unroll
    for (int i = 0; i < 4; i++)
#pragma unroll
        for (int j = 0; j < 4; j++) acc[i][j] = 0.f;

    for (int k0 = 0; k0 < ICC; k0 += BK) {
        for (int i = tid; i < BM * BK; i += 256) {
            int r = i / BK, k = i % BK;
            float v = 0.f;
            int row = row0 + r;
            if (row < NN) v = x[(size_t)row * ICC + k0 + k];
            As[k][r] = v;
        }
        for (int i = tid; i < BK * BN; i += 256) {
            int k = i / BN, c = i % BN;
            Bs[k][c] = W[(k0 + k) * HC + col0 + c];
        }
        __syncthreads();
#pragma unroll
        for (int k = 0; k < BK; k++) {
            float a[4], b[4];
#pragma unroll
            for (int i = 0; i < 4; i++) a[i] = As[k][ty * 4 + i];
#pragma unroll
            for (int j = 0; j < 4; j++) b[j] = Bs[k][tx * 4 + j];
#pragma unroll
            for (int i = 0; i < 4; i++)
#pragma unroll
                for (int j = 0; j < 4; j++) acc[i][j] += a[i] * b[j];
        }
        __syncthreads();
    }
#pragma unroll
    for (int i = 0; i < 4; i++) {
        int r = row0 + ty * 4 + i;
        if (r < NN) {
#pragma unroll
            for (int j = 0; j < 4; j++)
                g_h[(size_t)r * HC + col0 + tx * 4 + j] = acc[i][j];
        }
    }
}

// ---------------- K2: per-node attention logits a_src, a_dst ---------------
__global__ void k_att(const float* __restrict__ att_src,
                      const float* __restrict__ att_dst) {
    int warp = (blockIdx.x * blockDim.x + threadIdx.x) >> 5;
    int lane = threadIdx.x & 31;
    if (warp >= NN) return;
    const float* hr = g_h + (size_t)warp * HC;
#pragma unroll
    for (int hd = 0; hd < HEADS; hd++) {
        float v = hr[hd * OC + lane];
        float s = v * att_src[hd * OC + lane];
        float d = v * att_dst[hd * OC + lane];
#pragma unroll
        for (int o = 16; o; o >>= 1) {
            s += __shfl_xor_sync(0xffffffffu, s, o);
            d += __shfl_xor_sync(0xffffffffu, d, o);
        }
        if (lane == 0) {
            g_asrc[warp * HEADS + hd] = s;
            g_adst[warp * HEADS + hd] = d;
        }
    }
}

// ---------------- K3: segment max over dst ---------------------------------
__global__ void k_max(const void* __restrict__ ei) {
    long long i = (long long)blockIdx.x * blockDim.x + threadIdx.x;
    if (i >= (long long)TOT * HEADS) return;
    int e = (int)(i / HEADS), hd = (int)(i % HEADS);
    int src, dst;
    load_edge(ei, e, src, dst);
    if ((unsigned)src >= NN || (unsigned)dst >= NN) return;  // safety net
    float v = g_asrc[src * HEADS + hd] + g_adst[dst * HEADS + hd];
    v = v > 0.f ? v : NEG_SLOPE * v;
    atomicMax(&g_m[dst * HEADS + hd], f2ord(v));
}

// ---------------- K4: exp + segment sum ------------------------------------
__global__ void k_exp(const void* __restrict__ ei) {
    long long i = (long long)blockIdx.x * blockDim.x + threadIdx.x;
    if (i >= (long long)TOT * HEADS) return;
    int e = (int)(i / HEADS), hd = (int)(i % HEADS);
    int src, dst;
    load_edge(ei, e, src, dst);
    if ((unsigned)src >= NN || (unsigned)dst >= NN) return;  // safety net
    float v = g_asrc[src * HEADS + hd] + g_adst[dst * HEADS + hd];
    v = v > 0.f ? v : NEG_SLOPE * v;
    float m = ord2f(g_m[dst * HEADS + hd]);
    float ex = __expf(v - m);
    g_ex[(size_t)e * HEADS + hd] = ex;
    atomicAdd(&g_denom[dst * HEADS + hd], ex);
}

// ---------------- K5: weighted gather-scatter (sum over heads per edge) ----
__global__ void k_scatter(const void* __restrict__ ei) {
    int warp = blockIdx.x * (blockDim.x >> 5) + (threadIdx.x >> 5);
    int lane = threadIdx.x & 31;
    if (warp >= TOT) return;
    int src, dst;
    load_edge(ei, warp, src, dst);
    if ((unsigned)src >= NN || (unsigned)dst >= NN) return;  // safety net

    float exv = 0.f, dnv = 1.f;
    if (lane < HEADS) {
        exv = g_ex[(size_t)warp * HEADS + lane];
        dnv = g_denom[dst * HEADS + lane];
    }
    const float* hr = g_h + (size_t)src * HC;
    float acc = 0.f;
#pragma unroll
    for (int hd = 0; hd < HEADS; hd++) {
        float a = __shfl_sync(0xffffffffu, exv, hd) /
                  (__shfl_sync(0xffffffffu, dnv, hd) + 1e-16f);
        acc += a * hr[hd * OC + lane];
    }
    atomicAdd(&g_y[dst * OC + lane], acc);
}

// ---------------- K6: mean + bias + relu + MLP + residual relu -------------
__global__ void k_mlp(const float* __restrict__ bias,
                      const float* __restrict__ W1, const float* __restrict__ b1,
                      const float* __restrict__ W2, const float* __restrict__ b2,
                      float* __restrict__ out) {
    __shared__ float sW1[OC * 2 * OC];   // [32][64]
    __shared__ float sW2[2 * OC * OC];   // [64][32]
    __shared__ float sb1[2 * OC], sb2[OC], sbias[OC];
    for (int i = threadIdx.x; i < OC * 2 * OC; i += blockDim.x) {
        sW1[i] = W1[i];
        sW2[i] = W2[i];
    }
    for (int i = threadIdx.x; i < 2 * OC; i += blockDim.x) sb1[i] = b1[i];
    for (int i = threadIdx.x; i < OC; i += blockDim.x) { sb2[i] = b2[i]; sbias[i] = bias[i]; }
    __syncthreads();

    int nid = blockIdx.x * blockDim.x + threadIdx.x;
    if (nid >= NN) return;

    const float inv = 1.0f / (float)HEADS;
    float t[2 * OC];
#pragma unroll
    for (int j = 0; j < 2 * OC; j++) t[j] = sb1[j];

    for (int c = 0; c < OC; c++) {
        float yv = g_y[nid * OC + c] * inv + sbias[c];
        yv = yv > 0.f ? yv : 0.f;
#pragma unroll
        for (int j = 0; j < 2 * OC; j++) t[j] += yv * sW1[c * (2 * OC) + j];
    }
#pragma unroll
    for (int j = 0; j < 2 * OC; j++) t[j] = t[j] > 0.f ? t[j] : 0.f;

    for (int c = 0; c < OC; c++) {
        float z = sb2[c];
#pragma unroll
        for (int j = 0; j < 2 * OC; j++) z += t[j] * sW2[j * OC + c];
        float yv = g_y[nid * OC + c] * inv + sbias[c];
        yv = yv > 0.f ? yv : 0.f;
        float r = yv + z;
        out[nid * OC + c] = r > 0.f ? r : 0.f;
    }
}

// ---------------- launch -----------------------------------------------------
extern "C" void kernel_launch(void* const* d_in, const int* in_sizes, int n_in,
                              void* d_out, int out_size) {
    const float* x       = (const float*)d_in[0];
    const void*  ei      = d_in[1];
    const float* W       = (const float*)d_in[2];
    const float* att_src = (const float*)d_in[3];
    const float* att_dst = (const float*)d_in[4];
    const float* bias    = (const float*)d_in[5];
    const float* W1      = (const float*)d_in[6];
    const float* b1      = (const float*)d_in[7];
    const float* W2      = (const float*)d_in[8];
    const float* b2      = (const float*)d_in[9];
    float*       out     = (float*)d_out;

    // K-1: dtype detection (reads only first 256 bytes of edge_index)
    k_detect<<<1, 32>>>((const int*)ei);

    // K0: init
    k_init<<<(NN * OC + 255) / 256, 256>>>();

    // K1: h = x @ W
    dim3 ggrid(HC / BN, (NN + BM - 1) / BM);
    k_gemm<<<ggrid, 256>>>(x, W);

    // K2: attention logits (warp per node)
    k_att<<<(NN * 32 + 255) / 256, 256>>>(att_src, att_dst);

    // K3: segment max
    long long nwork = (long long)TOT * HEADS;
    int blks = (int)((nwork + 255) / 256);
    k_max<<<blks, 256>>>(ei);

    // K4: exp + denom
    k_exp<<<blks, 256>>>(ei);

    // K5: gather-scatter (warp per edge)
    int sblks = (TOT + 7) / 8;  // 8 warps per 256-thread block
    k_scatter<<<sblks, 256>>>(ei);

    // K6: epilogue MLP
    k_mlp<<<(NN + 127) / 128, 128>>>(bias, W1, b1, W2, b2, out);
}

// round 4
// speedup vs baseline: 1.2679x; 1.2679x over previous
#include <cuda_runtime.h>
#include <cuda_bf16.h>
#include <cstdint>

// Problem constants (fixed shapes per reference)
#define NN    50000
#define EE    800000
#define TOT   (EE + NN)      // edges + self loops
#define HEADS 12
#define OC    32
#define ICC   128
#define HC    (HEADS * OC)   // 384
#define NEG_SLOPE 0.2f

#define BMM   64             // CTA M tile
#define BNN   64             // CTA N tile (= 2 heads)
#define LDA   136            // smem row stride in bf16 elems (128 + 8 pad)

// ---------------- scratch (device globals; no allocations allowed) ----------
__device__ float         g_h[(size_t)NN * HC];      // 76.8 MB  h = x@W
__device__ float         g_asrc[NN * HEADS];
__device__ float         g_adst[NN * HEADS];
__device__ float         g_denom[NN * HEADS];       // softmax denominators
__device__ float         g_ex[(size_t)TOT * HEADS]; // exp(e)
__device__ float         g_y[NN * OC];              // head-sum accumulator
__device__ int           g_is64;                    // edge_index dtype flag
__device__ __nv_bfloat16 g_wt_hi[HC * ICC];         // W^T hi, [n][k]
__device__ __nv_bfloat16 g_wt_lo[HC * ICC];         // W^T lo

// Load edge e's (src, dst), robust to int32 vs int64 edge_index.
__device__ __forceinline__ void load_edge(const void* __restrict__ ei, int e,
                                          int& src, int& dst) {
    if (e >= EE) { src = dst = e - EE; return; }   // self-loop
    if (g_is64) {
        const long long* p = (const long long*)ei;
        src = (int)p[e];
        dst = (int)p[EE + e];
    } else {
        const int* p = (const int*)ei;
        src = p[e];
        dst = p[EE + e];
    }
}

__device__ __forceinline__ uint32_t smem_u32(const void* p) {
    uint32_t a;
    asm("{ .reg .u64 t; cvta.to.shared.u64 t, %1; cvt.u32.u64 %0, t; }" : "=r"(a) : "l"(p));
    return a;
}

// ---------------- K-1: detect edge_index dtype ------------------------------
__global__ void k_detect(const int* __restrict__ ei32) {
    if (threadIdx.x == 0 && blockIdx.x == 0) {
        bool hi_all_zero = true;
        for (int i = 0; i < 32; i++)
            if (ei32[2 * i + 1] != 0) hi_all_zero = false;
        g_is64 = hi_all_zero ? 1 : 0;
    }
}

// ---------------- K0: init accumulators ------------------------------------
__global__ void k_init() {
    int i = blockIdx.x * blockDim.x + threadIdx.x;
    if (i < NN * OC) g_y[i] = 0.f;
    if (i < NN * HEADS) g_denom[i] = 0.f;
}

// ---------------- K0b: split W^T into bf16 hi/lo, [n][k] layout ------------
__global__ void k_prep(const float* __restrict__ W) {
    int i = blockIdx.x * blockDim.x + threadIdx.x;
    if (i >= HC * ICC) return;
    int n = i / ICC, k = i % ICC;
    float v = W[k * HC + n];
    __nv_bfloat16 hi = __float2bfloat16(v);
    float rem = v - __bfloat162float(hi);
    g_wt_hi[n * ICC + k] = hi;
    g_wt_lo[n * ICC + k] = __float2bfloat16(rem);
}

// ---------------- K1: h = x @ W via mma.sync bf16 3-term, fused att logits --
// smem (dynamic): aHi[64*136] aLo bHi bLo  (bf16)
#define SMB_AHI 0
#define SMB_ALO (BMM * LDA * 2)
#define SMB_BHI (2 * BMM * LDA * 2)
#define SMB_BLO (3 * BMM * LDA * 2)
#define SM_GEMM (4 * BMM * LDA * 2)

__device__ __forceinline__ void ldm_x4(uint32_t addr, uint32_t& r0, uint32_t& r1,
                                       uint32_t& r2, uint32_t& r3) {
    asm volatile("ldmatrix.sync.aligned.m8n8.x4.shared.b16 {%0,%1,%2,%3}, [%4];"
                 : "=r"(r0), "=r"(r1), "=r"(r2), "=r"(r3) : "r"(addr));
}
__device__ __forceinline__ void ldm_x2(uint32_t addr, uint32_t& r0, uint32_t& r1) {
    asm volatile("ldmatrix.sync.aligned.m8n8.x2.shared.b16 {%0,%1}, [%2];"
                 : "=r"(r0), "=r"(r1) : "r"(addr));
}
__device__ __forceinline__ void mma_bf16(float* d, uint32_t a0, uint32_t a1,
                                         uint32_t a2, uint32_t a3,
                                         uint32_t b0, uint32_t b1) {
    asm volatile(
        "mma.sync.aligned.m16n8k16.row.col.f32.bf16.bf16.f32 "
        "{%0,%1,%2,%3}, {%4,%5,%6,%7}, {%8,%9}, {%0,%1,%2,%3};"
        : "+f"(d[0]), "+f"(d[1]), "+f"(d[2]), "+f"(d[3])
        : "r"(a0), "r"(a1), "r"(a2), "r"(a3), "r"(b0), "r"(b1));
}

__global__ void __launch_bounds__(128) k_gemm_mma(const float* __restrict__ x,
                                                  const float* __restrict__ att_src,
                                                  const float* __restrict__ att_dst) {
    extern __shared__ char smem[];
    __nv_bfloat16* aHi = (__nv_bfloat16*)(smem + SMB_AHI);
    __nv_bfloat16* aLo = (__nv_bfloat16*)(smem + SMB_ALO);
    __nv_bfloat16* bHi = (__nv_bfloat16*)(smem + SMB_BHI);
    __nv_bfloat16* bLo = (__nv_bfloat16*)(smem + SMB_BLO);

    const int tid = threadIdx.x;
    const int wid = tid >> 5, lane = tid & 31;
    const int row0 = blockIdx.x * BMM;
    const int n0 = blockIdx.y * BNN;         // global col base (head pair)

    // ---- load A tile (64 rows x 128 fp32) -> bf16 hi/lo in smem ----
#pragma unroll
    for (int j = 0; j < 16; j++) {
        int s = tid + j * 128;               // 2048 float4 slots
        int r = s >> 5, c = (s & 31) << 2;
        float4 v = make_float4(0.f, 0.f, 0.f, 0.f);
        int grow = row0 + r;
        if (grow < NN) v = *(const float4*)(x + (size_t)grow * ICC + c);
        __nv_bfloat16 h0 = __float2bfloat16(v.x), h1 = __float2bfloat16(v.y);
        __nv_bfloat16 h2 = __float2bfloat16(v.z), h3 = __float2bfloat16(v.w);
        aHi[r * LDA + c + 0] = h0; aHi[r * LDA + c + 1] = h1;
        aHi[r * LDA + c + 2] = h2; aHi[r * LDA + c + 3] = h3;
        aLo[r * LDA + c + 0] = __float2bfloat16(v.x - __bfloat162float(h0));
        aLo[r * LDA + c + 1] = __float2bfloat16(v.y - __bfloat162float(h1));
        aLo[r * LDA + c + 2] = __float2bfloat16(v.z - __bfloat162float(h2));
        aLo[r * LDA + c + 3] = __float2bfloat16(v.w - __bfloat162float(h3));
    }
    // ---- load B tile (rows n0..n0+63 of W^T, 128 cols) ----
#pragma unroll
    for (int j = 0; j < 8; j++) {
        int s = tid + j * 128;               // 1024 uint4 slots (8 bf16 each)
        int r = s >> 4, c = (s & 15) << 3;
        *(uint4*)(bHi + r * LDA + c) = *(const uint4*)(g_wt_hi + (n0 + r) * ICC + c);
        *(uint4*)(bLo + r * LDA + c) = *(const uint4*)(g_wt_lo + (n0 + r) * ICC + c);
    }
    __syncthreads();

    const int warpM = wid * 16;
    float acc[8][4];
#pragma unroll
    for (int nt = 0; nt < 8; nt++)
#pragma unroll
        for (int j = 0; j < 4; j++) acc[nt][j] = 0.f;

    const uint32_t aHiB = smem_u32(aHi), aLoB = smem_u32(aLo);
    const uint32_t bHiB = smem_u32(bHi), bLoB = smem_u32(bLo);
    const int arow = warpM + (lane & 15);
    const int akoff = (lane >> 4) * 8;
    const int brow0 = lane & 7;
    const int bkoff = (lane & 8);            // 0 or 8

#pragma unroll
    for (int kc = 0; kc < 8; kc++) {
        uint32_t ah0, ah1, ah2, ah3, al0, al1, al2, al3;
        uint32_t aoff = (uint32_t)((arow * LDA + kc * 16 + akoff) * 2);
        ldm_x4(aHiB + aoff, ah0, ah1, ah2, ah3);
        ldm_x4(aLoB + aoff, al0, al1, al2, al3);
#pragma unroll
        for (int nt = 0; nt < 8; nt++) {
            uint32_t boff = (uint32_t)(((nt * 8 + brow0) * LDA + kc * 16 + bkoff) * 2);
            uint32_t bh0, bh1, bl0, bl1;
            ldm_x2(bHiB + boff, bh0, bh1);
            ldm_x2(bLoB + boff, bl0, bl1);
            mma_bf16(acc[nt], ah0, ah1, ah2, ah3, bh0, bh1);
            mma_bf16(acc[nt], ah0, ah1, ah2, ah3, bl0, bl1);
            mma_bf16(acc[nt], al0, al1, al2, al3, bh0, bh1);
        }
    }

    // ---- epilogue: store h, fused attention logits for the 2 heads ----
    const int r1 = warpM + (lane >> 2);       // row within tile
    const int r2 = r1 + 8;
    const int grow1 = row0 + r1, grow2 = row0 + r2;
    const int cb = (lane & 3) * 2;            // col pair offset within n-tile
    const int hd0 = blockIdx.y * 2, hd1 = hd0 + 1;

    float s1h0 = 0.f, d1h0 = 0.f, s2h0 = 0.f, d2h0 = 0.f;
    float s1h1 = 0.f, d1h1 = 0.f, s2h1 = 0.f, d2h1 = 0.f;
#pragma unroll
    for (int nt = 0; nt < 8; nt++) {
        int gcol = n0 + nt * 8 + cb;
        if (grow1 < NN)
            *(float2*)(g_h + (size_t)grow1 * HC + gcol) = make_float2(acc[nt][0], acc[nt][1]);
        if (grow2 < NN)
            *(float2*)(g_h + (size_t)grow2 * HC + gcol) = make_float2(acc[nt][2], acc[nt][3]);
        float as0 = __ldg(att_src + gcol), as1 = __ldg(att_src + gcol + 1);
        float ad0 = __ldg(att_dst + gcol), ad1 = __ldg(att_dst + gcol + 1);
        if (nt < 4) {
            s1h0 += acc[nt][0] * as0 + acc[nt][1] * as1;
            d1h0 += acc[nt][0] * ad0 + acc[nt][1] * ad1;
            s2h0 += acc[nt][2] * as0 + acc[nt][3] * as1;
            d2h0 += acc[nt][2] * ad0 + acc[nt][3] * ad1;
        } else {
            s1h1 += acc[nt][0] * as0 + acc[nt][1] * as1;
            d1h1 += acc[nt][0] * ad0 + acc[nt][1] * ad1;
            s2h1 += acc[nt][2] * as0 + acc[nt][3] * as1;
            d2h1 += acc[nt][2] * ad0 + acc[nt][3] * ad1;
        }
    }
    // reduce across the 4 threads of each row group (lane%4)
#pragma unroll
    for (int o = 1; o <= 2; o <<= 1) {
        s1h0 += __shfl_xor_sync(0xffffffffu, s1h0, o);
        d1h0 += __shfl_xor_sync(0xffffffffu, d1h0, o);
        s2h0 += __shfl_xor_sync(0xffffffffu, s2h0, o);
        d2h0 += __shfl_xor_sync(0xffffffffu, d2h0, o);
        s1h1 += __shfl_xor_sync(0xffffffffu, s1h1, o);
        d1h1 += __shfl_xor_sync(0xffffffffu, d1h1, o);
        s2h1 += __shfl_xor_sync(0xffffffffu, s2h1, o);
        d2h1 += __shfl_xor_sync(0xffffffffu, d2h1, o);
    }
    if ((lane & 3) == 0) {
        if (grow1 < NN) {
            g_asrc[grow1 * HEADS + hd0] = s1h0;
            g_adst[grow1 * HEADS + hd0] = d1h0;
            g_asrc[grow1 * HEADS + hd1] = s1h1;
            g_adst[grow1 * HEADS + hd1] = d1h1;
        }
        if (grow2 < NN) {
            g_asrc[grow2 * HEADS + hd0] = s2h0;
            g_adst[grow2 * HEADS + hd0] = d2h0;
            g_asrc[grow2 * HEADS + hd1] = s2h1;
            g_adst[grow2 * HEADS + hd1] = d2h1;
        }
    }
}

// ---------------- K4: exp + segment sum (unshifted softmax) ----------------
__global__ void k_exp(const void* __restrict__ ei) {
    long long i = (long long)blockIdx.x * blockDim.x + threadIdx.x;
    if (i >= (long long)TOT * HEADS) return;
    int e = (int)(i / HEADS), hd = (int)(i % HEADS);
    int src, dst;
    load_edge(ei, e, src, dst);
    if ((unsigned)src >= NN || (unsigned)dst >= NN) return;  // safety net
    float v = g_asrc[src * HEADS + hd] + g_adst[dst * HEADS + hd];
    v = v > 0.f ? v : NEG_SLOPE * v;
    float ex = __expf(v);
    g_ex[(size_t)e * HEADS + hd] = ex;
    atomicAdd(&g_denom[dst * HEADS + hd], ex);
}

// ---------------- K5: weighted gather-scatter (sum over heads per edge) ----
__global__ void k_scatter(const void* __restrict__ ei) {
    int warp = blockIdx.x * (blockDim.x >> 5) + (threadIdx.x >> 5);
    int lane = threadIdx.x & 31;
    if (warp >= TOT) return;
    int src, dst;
    load_edge(ei, warp, src, dst);
    if ((unsigned)src >= NN || (unsigned)dst >= NN) return;  // safety net

    float exv = 0.f, dnv = 1.f;
    if (lane < HEADS) {
        exv = g_ex[(size_t)warp * HEADS + lane];
        dnv = g_denom[dst * HEADS + lane];
    }
    const float* hr = g_h + (size_t)src * HC;
    float acc = 0.f;
#pragma unroll
    for (int hd = 0; hd < HEADS; hd++) {
        float a = __shfl_sync(0xffffffffu, exv, hd) /
                  (__shfl_sync(0xffffffffu, dnv, hd) + 1e-16f);
        acc += a * hr[hd * OC + lane];
    }
    atomicAdd(&g_y[dst * OC + lane], acc);
}

// ---------------- K6: mean + bias + relu + MLP + residual relu -------------
__global__ void k_mlp(const float* __restrict__ bias,
                      const float* __restrict__ W1, const float* __restrict__ b1,
                      const float* __restrict__ W2, const float* __restrict__ b2,
                      float* __restrict__ out) {
    __shared__ float sW1[OC * 2 * OC];
    __shared__ float sW2[2 * OC * OC];
    __shared__ float sb1[2 * OC], sb2[OC], sbias[OC];
    for (int i = threadIdx.x; i < OC * 2 * OC; i += blockDim.x) {
        sW1[i] = W1[i];
        sW2[i] = W2[i];
    }
    for (int i = threadIdx.x; i < 2 * OC; i += blockDim.x) sb1[i] = b1[i];
    for (int i = threadIdx.x; i < OC; i += blockDim.x) { sb2[i] = b2[i]; sbias[i] = bias[i]; }
    __syncthreads();

    int nid = blockIdx.x * blockDim.x + threadIdx.x;
    if (nid >= NN) return;

    const float inv = 1.0f / (float)HEADS;
    float t[2 * OC];
#pragma unroll
    for (int j = 0; j < 2 * OC; j++) t[j] = sb1[j];

    for (int c = 0; c < OC; c++) {
        float yv = g_y[nid * OC + c] * inv + sbias[c];
        yv = yv > 0.f ? yv : 0.f;
#pragma unroll
        for (int j = 0; j < 2 * OC; j++) t[j] += yv * sW1[c * (2 * OC) + j];
    }
#pragma unroll
    for (int j = 0; j < 2 * OC; j++) t[j] = t[j] > 0.f ? t[j] : 0.f;

    for (int c = 0; c < OC; c++) {
        float z = sb2[c];
#pragma unroll
        for (int j = 0; j < 2 * OC; j++) z += t[j] * sW2[j * OC + c];
        float yv = g_y[nid * OC + c] * inv + sbias[c];
        yv = yv > 0.f ? yv : 0.f;
        float rr = yv + z;
        out[nid * OC + c] = rr > 0.f ? rr : 0.f;
    }
}

// ---------------- launch -----------------------------------------------------
extern "C" void kernel_launch(void* const* d_in, const int* in_sizes, int n_in,
                              void* d_out, int out_size) {
    const float* x       = (const float*)d_in[0];
    const void*  ei      = d_in[1];
    const float* W       = (const float*)d_in[2];
    const float* att_src = (const float*)d_in[3];
    const float* att_dst = (const float*)d_in[4];
    const float* bias    = (const float*)d_in[5];
    const float* W1      = (const float*)d_in[6];
    const float* b1      = (const float*)d_in[7];
    const float* W2      = (const float*)d_in[8];
    const float* b2      = (const float*)d_in[9];
    float*       out     = (float*)d_out;

    static bool attr_done = false;
    if (!attr_done) {
        cudaFuncSetAttribute(k_gemm_mma, cudaFuncAttributeMaxDynamicSharedMemorySize,
                             SM_GEMM);
        attr_done = true;
    }

    k_detect<<<1, 32>>>((const int*)ei);
    k_init<<<(NN * OC + 255) / 256, 256>>>();
    k_prep<<<(HC * ICC + 255) / 256, 256>>>(W);

    // fused GEMM + attention logits
    dim3 ggrid((NN + BMM - 1) / BMM, HC / BNN);
    k_gemm_mma<<<ggrid, 128, SM_GEMM>>>(x, att_src, att_dst);

    // exp + denom (unshifted softmax)
    long long nwork = (long long)TOT * HEADS;
    int blks = (int)((nwork + 255) / 256);
    k_exp<<<blks, 256>>>(ei);

    // gather-scatter (warp per edge)
    int sblks = (TOT + 7) / 8;
    k_scatter<<<sblks, 256>>>(ei);

    // epilogue MLP
    k_mlp<<<(NN + 127) / 128, 128>>>(bias, W1, b1, W2, b2, out);
}

// round 5
// speedup vs baseline: 2.0199x; 1.5932x over previous
#include <cuda_runtime.h>
#include <cuda_bf16.h>
#include <cstdint>

// Problem constants (fixed shapes per reference)
#define NN    50000
#define EE    800000
#define HEADS 12
#define OC    32
#define ICC   128
#define HC    (HEADS * OC)   // 384
#define NEG_SLOPE 0.2f

#define BMM   64             // CTA M tile
#define BNN   64             // CTA N tile (= 2 heads)
#define LDA   136            // smem row stride in bf16 elems (128 + 8 pad)

// ---------------- scratch (device globals; no allocations allowed) ----------
__device__ float         g_h[(size_t)NN * HC];      // 76.8 MB  h = x@W
__device__ float         g_asrc[NN * HEADS];
__device__ float         g_adst[NN * HEADS];
__device__ float         g_y[NN * OC];              // aggregated output (no atomics)
__device__ int           g_is64;                    // edge_index dtype flag
__device__ __nv_bfloat16 g_wt_hi[HC * ICC];         // W^T hi, [n][k]
__device__ __nv_bfloat16 g_wt_lo[HC * ICC];         // W^T lo
// CSR-by-dst structures
__device__ int g_cnt[NN];        // in-degree (real edges only)
__device__ int g_rowptr[NN];     // exclusive prefix
__device__ int g_cursor[NN];     // fill cursors
__device__ int g_csr[EE];        // src ids grouped by dst

__device__ __forceinline__ void load_edge(const void* __restrict__ ei, int e,
                                          int& src, int& dst) {
    if (g_is64) {
        const long long* p = (const long long*)ei;
        src = (int)p[e];
        dst = (int)p[EE + e];
    } else {
        const int* p = (const int*)ei;
        src = p[e];
        dst = p[EE + e];
    }
}

__device__ __forceinline__ uint32_t smem_u32(const void* p) {
    uint32_t a;
    asm("{ .reg .u64 t; cvta.to.shared.u64 t, %1; cvt.u32.u64 %0, t; }" : "=r"(a) : "l"(p));
    return a;
}

// ---------------- K-1: detect edge_index dtype ------------------------------
__global__ void k_detect(const int* __restrict__ ei32) {
    if (threadIdx.x == 0 && blockIdx.x == 0) {
        bool hi_all_zero = true;
        for (int i = 0; i < 32; i++)
            if (ei32[2 * i + 1] != 0) hi_all_zero = false;
        g_is64 = hi_all_zero ? 1 : 0;
    }
}

// ---------------- K0: zero degree counters ----------------------------------
__global__ void k_init() {
    int i = blockIdx.x * blockDim.x + threadIdx.x;
    if (i < NN) g_cnt[i] = 0;
}

// ---------------- K0b: split W^T into bf16 hi/lo, [n][k] layout ------------
__global__ void k_prep(const float* __restrict__ W) {
    int i = blockIdx.x * blockDim.x + threadIdx.x;
    if (i >= HC * ICC) return;
    int n = i / ICC, k = i % ICC;
    float v = W[k * HC + n];
    __nv_bfloat16 hi = __float2bfloat16(v);
    float rem = v - __bfloat162float(hi);
    g_wt_hi[n * ICC + k] = hi;
    g_wt_lo[n * ICC + k] = __float2bfloat16(rem);
}

// ---------------- CSR build --------------------------------------------------
__global__ void k_hist(const void* __restrict__ ei) {
    int e = blockIdx.x * blockDim.x + threadIdx.x;
    if (e >= EE) return;
    int src, dst;
    load_edge(ei, e, src, dst);
    if ((unsigned)dst < NN) atomicAdd(&g_cnt[dst], 1);
}

__global__ void k_scan() {   // single block, 1024 threads
    __shared__ int s[1024];
    __shared__ int carry_s;
    int tid = threadIdx.x;
    if (tid == 0) carry_s = 0;
    __syncthreads();
    for (int c0 = 0; c0 < NN; c0 += 1024) {
        int idx = c0 + tid;
        int v = (idx < NN) ? g_cnt[idx] : 0;
        s[tid] = v;
        __syncthreads();
        for (int off = 1; off < 1024; off <<= 1) {
            int t = (tid >= off) ? s[tid - off] : 0;
            __syncthreads();
            s[tid] += t;
            __syncthreads();
        }
        int excl = s[tid] - v + carry_s;
        if (idx < NN) { g_rowptr[idx] = excl; g_cursor[idx] = excl; }
        __syncthreads();
        if (tid == 1023) carry_s += s[1023];
        __syncthreads();
    }
}

__global__ void k_fill(const void* __restrict__ ei) {
    int e = blockIdx.x * blockDim.x + threadIdx.x;
    if (e >= EE) return;
    int src, dst;
    load_edge(ei, e, src, dst);
    if ((unsigned)src >= NN || (unsigned)dst >= NN) return;
    int pos = atomicAdd(&g_cursor[dst], 1);
    g_csr[pos] = src;
}

// ---------------- K1: h = x @ W via mma.sync bf16 3-term, fused att logits --
#define SMB_AHI 0
#define SMB_ALO (BMM * LDA * 2)
#define SMB_BHI (2 * BMM * LDA * 2)
#define SMB_BLO (3 * BMM * LDA * 2)
#define SM_GEMM (4 * BMM * LDA * 2)

__device__ __forceinline__ void ldm_x4(uint32_t addr, uint32_t& r0, uint32_t& r1,
                                       uint32_t& r2, uint32_t& r3) {
    asm volatile("ldmatrix.sync.aligned.m8n8.x4.shared.b16 {%0,%1,%2,%3}, [%4];"
                 : "=r"(r0), "=r"(r1), "=r"(r2), "=r"(r3) : "r"(addr));
}
__device__ __forceinline__ void ldm_x2(uint32_t addr, uint32_t& r0, uint32_t& r1) {
    asm volatile("ldmatrix.sync.aligned.m8n8.x2.shared.b16 {%0,%1}, [%2];"
                 : "=r"(r0), "=r"(r1) : "r"(addr));
}
__device__ __forceinline__ void mma_bf16(float* d, uint32_t a0, uint32_t a1,
                                         uint32_t a2, uint32_t a3,
                                         uint32_t b0, uint32_t b1) {
    asm volatile(
        "mma.sync.aligned.m16n8k16.row.col.f32.bf16.bf16.f32 "
        "{%0,%1,%2,%3}, {%4,%5,%6,%7}, {%8,%9}, {%0,%1,%2,%3};"
        : "+f"(d[0]), "+f"(d[1]), "+f"(d[2]), "+f"(d[3])
        : "r"(a0), "r"(a1), "r"(a2), "r"(a3), "r"(b0), "r"(b1));
}

__global__ void __launch_bounds__(128) k_gemm_mma(const float* __restrict__ x,
                                                  const float* __restrict__ att_src,
                                                  const float* __restrict__ att_dst) {
    extern __shared__ char smem[];
    __nv_bfloat16* aHi = (__nv_bfloat16*)(smem + SMB_AHI);
    __nv_bfloat16* aLo = (__nv_bfloat16*)(smem + SMB_ALO);
    __nv_bfloat16* bHi = (__nv_bfloat16*)(smem + SMB_BHI);
    __nv_bfloat16* bLo = (__nv_bfloat16*)(smem + SMB_BLO);

    const int tid = threadIdx.x;
    const int wid = tid >> 5, lane = tid & 31;
    const int row0 = blockIdx.x * BMM;
    const int n0 = blockIdx.y * BNN;

#pragma unroll
    for (int j = 0; j < 16; j++) {
        int s = tid + j * 128;
        int r = s >> 5, c = (s & 31) << 2;
        float4 v = make_float4(0.f, 0.f, 0.f, 0.f);
        int grow = row0 + r;
        if (grow < NN) v = *(const float4*)(x + (size_t)grow * ICC + c);
        __nv_bfloat16 h0 = __float2bfloat16(v.x), h1 = __float2bfloat16(v.y);
        __nv_bfloat16 h2 = __float2bfloat16(v.z), h3 = __float2bfloat16(v.w);
        aHi[r * LDA + c + 0] = h0; aHi[r * LDA + c + 1] = h1;
        aHi[r * LDA + c + 2] = h2; aHi[r * LDA + c + 3] = h3;
        aLo[r * LDA + c + 0] = __float2bfloat16(v.x - __bfloat162float(h0));
        aLo[r * LDA + c + 1] = __float2bfloat16(v.y - __bfloat162float(h1));
        aLo[r * LDA + c + 2] = __float2bfloat16(v.z - __bfloat162float(h2));
        aLo[r * LDA + c + 3] = __float2bfloat16(v.w - __bfloat162float(h3));
    }
#pragma unroll
    for (int j = 0; j < 8; j++) {
        int s = tid + j * 128;
        int r = s >> 4, c = (s & 15) << 3;
        *(uint4*)(bHi + r * LDA + c) = *(const uint4*)(g_wt_hi + (n0 + r) * ICC + c);
        *(uint4*)(bLo + r * LDA + c) = *(const uint4*)(g_wt_lo + (n0 + r) * ICC + c);
    }
    __syncthreads();

    const int warpM = wid * 16;
    float acc[8][4];
#pragma unroll
    for (int nt = 0; nt < 8; nt++)
#pragma unroll
        for (int j = 0; j < 4; j++) acc[nt][j] = 0.f;

    const uint32_t aHiB = smem_u32(aHi), aLoB = smem_u32(aLo);
    const uint32_t bHiB = smem_u32(bHi), bLoB = smem_u32(bLo);
    const int arow = warpM + (lane & 15);
    const int akoff = (lane >> 4) * 8;
    const int brow0 = lane & 7;
    const int bkoff = (lane & 8);

#pragma unroll
    for (int kc = 0; kc < 8; kc++) {
        uint32_t ah0, ah1, ah2, ah3, al0, al1, al2, al3;
        uint32_t aoff = (uint32_t)((arow * LDA + kc * 16 + akoff) * 2);
        ldm_x4(aHiB + aoff, ah0, ah1, ah2, ah3);
        ldm_x4(aLoB + aoff, al0, al1, al2, al3);
#pragma unroll
        for (int nt = 0; nt < 8; nt++) {
            uint32_t boff = (uint32_t)(((nt * 8 + brow0) * LDA + kc * 16 + bkoff) * 2);
            uint32_t bh0, bh1, bl0, bl1;
            ldm_x2(bHiB + boff, bh0, bh1);
            ldm_x2(bLoB + boff, bl0, bl1);
            mma_bf16(acc[nt], ah0, ah1, ah2, ah3, bh0, bh1);
            mma_bf16(acc[nt], ah0, ah1, ah2, ah3, bl0, bl1);
            mma_bf16(acc[nt], al0, al1, al2, al3, bh0, bh1);
        }
    }

    const int r1 = warpM + (lane >> 2);
    const int r2 = r1 + 8;
    const int grow1 = row0 + r1, grow2 = row0 + r2;
    const int cb = (lane & 3) * 2;
    const int hd0 = blockIdx.y * 2, hd1 = hd0 + 1;

    float s1h0 = 0.f, d1h0 = 0.f, s2h0 = 0.f, d2h0 = 0.f;
    float s1h1 = 0.f, d1h1 = 0.f, s2h1 = 0.f, d2h1 = 0.f;
#pragma unroll
    for (int nt = 0; nt < 8; nt++) {
        int gcol = n0 + nt * 8 + cb;
        if (grow1 < NN)
            *(float2*)(g_h + (size_t)grow1 * HC + gcol) = make_float2(acc[nt][0], acc[nt][1]);
        if (grow2 < NN)
            *(float2*)(g_h + (size_t)grow2 * HC + gcol) = make_float2(acc[nt][2], acc[nt][3]);
        float as0 = __ldg(att_src + gcol), as1 = __ldg(att_src + gcol + 1);
        float ad0 = __ldg(att_dst + gcol), ad1 = __ldg(att_dst + gcol + 1);
        if (nt < 4) {
            s1h0 += acc[nt][0] * as0 + acc[nt][1] * as1;
            d1h0 += acc[nt][0] * ad0 + acc[nt][1] * ad1;
            s2h0 += acc[nt][2] * as0 + acc[nt][3] * as1;
            d2h0 += acc[nt][2] * ad0 + acc[nt][3] * ad1;
        } else {
            s1h1 += acc[nt][0] * as0 + acc[nt][1] * as1;
            d1h1 += acc[nt][0] * ad0 + acc[nt][1] * ad1;
            s2h1 += acc[nt][2] * as0 + acc[nt][3] * as1;
            d2h1 += acc[nt][2] * ad0 + acc[nt][3] * ad1;
        }
    }
#pragma unroll
    for (int o = 1; o <= 2; o <<= 1) {
        s1h0 += __shfl_xor_sync(0xffffffffu, s1h0, o);
        d1h0 += __shfl_xor_sync(0xffffffffu, d1h0, o);
        s2h0 += __shfl_xor_sync(0xffffffffu, s2h0, o);
        d2h0 += __shfl_xor_sync(0xffffffffu, d2h0, o);
        s1h1 += __shfl_xor_sync(0xffffffffu, s1h1, o);
        d1h1 += __shfl_xor_sync(0xffffffffu, d1h1, o);
        s2h1 += __shfl_xor_sync(0xffffffffu, s2h1, o);
        d2h1 += __shfl_xor_sync(0xffffffffu, d2h1, o);
    }
    if ((lane & 3) == 0) {
        if (grow1 < NN) {
            g_asrc[grow1 * HEADS + hd0] = s1h0;
            g_adst[grow1 * HEADS + hd0] = d1h0;
            g_asrc[grow1 * HEADS + hd1] = s1h1;
            g_adst[grow1 * HEADS + hd1] = d1h1;
        }
        if (grow2 < NN) {
            g_asrc[grow2 * HEADS + hd0] = s2h0;
            g_adst[grow2 * HEADS + hd0] = d2h0;
            g_asrc[grow2 * HEADS + hd1] = s2h1;
            g_adst[grow2 * HEADS + hd1] = d2h1;
        }
    }
}

// ---------------- K5: CSR aggregation, warp per dst node -------------------
__device__ __forceinline__ float leaky(float v) {
    return v > 0.f ? v : NEG_SLOPE * v;
}

__global__ void __launch_bounds__(256) k_aggr() {
    int n = blockIdx.x * (blockDim.x >> 5) + (threadIdx.x >> 5);
    int lane = threadIdx.x & 31;
    if (n >= NN) return;

    int base = g_rowptr[n];
    int deg = g_cnt[n];

    float adst = (lane < HEADS) ? g_adst[n * HEADS + lane] : 0.f;
    float asrc_self = (lane < HEADS) ? g_asrc[n * HEADS + lane] : 0.f;

    // ---- pass 1: softmax denominator per head (lane = head) ----
    float denom = (lane < HEADS) ? __expf(leaky(asrc_self + adst)) : 0.f;
    for (int i0 = 0; i0 < deg; i0 += 32) {
        int s_i = (i0 + lane < deg) ? g_csr[base + i0 + lane] : 0;
        int cnt = min(32, deg - i0);
        for (int j = 0; j < cnt; j++) {
            int src = __shfl_sync(0xffffffffu, s_i, j);
            float as = (lane < HEADS) ? g_asrc[src * HEADS + lane] : 0.f;
            if (lane < HEADS) denom += __expf(leaky(as + adst));
        }
    }
    denom += 1e-16f;

    // ---- pass 2: weighted aggregation (lane = channel) ----
    float acc = 0.f;
    {   // self loop
        float al = (lane < HEADS) ? __expf(leaky(asrc_self + adst)) / denom : 0.f;
        const float* hr = g_h + (size_t)n * HC;
#pragma unroll
        for (int hd = 0; hd < HEADS; hd++) {
            float a = __shfl_sync(0xffffffffu, al, hd);
            acc += a * hr[hd * OC + lane];
        }
    }
    for (int i0 = 0; i0 < deg; i0 += 32) {
        int s_i = (i0 + lane < deg) ? g_csr[base + i0 + lane] : 0;
        int cnt = min(32, deg - i0);
        for (int j = 0; j < cnt; j++) {
            int src = __shfl_sync(0xffffffffu, s_i, j);
            float as = (lane < HEADS) ? g_asrc[src * HEADS + lane] : 0.f;
            float al = (lane < HEADS) ? __expf(leaky(as + adst)) / denom : 0.f;
            const float* hr = g_h + (size_t)src * HC;
#pragma unroll
            for (int hd = 0; hd < HEADS; hd++) {
                float a = __shfl_sync(0xffffffffu, al, hd);
                acc += a * hr[hd * OC + lane];
            }
        }
    }
    g_y[n * OC + lane] = acc;
}

// ---------------- K6: mean + bias + relu + MLP + residual relu -------------
__global__ void k_mlp(const float* __restrict__ bias,
                      const float* __restrict__ W1, const float* __restrict__ b1,
                      const float* __restrict__ W2, const float* __restrict__ b2,
                      float* __restrict__ out) {
    __shared__ float sW1[OC * 2 * OC];
    __shared__ float sW2[2 * OC * OC];
    __shared__ float sb1[2 * OC], sb2[OC], sbias[OC];
    for (int i = threadIdx.x; i < OC * 2 * OC; i += blockDim.x) {
        sW1[i] = W1[i];
        sW2[i] = W2[i];
    }
    for (int i = threadIdx.x; i < 2 * OC; i += blockDim.x) sb1[i] = b1[i];
    for (int i = threadIdx.x; i < OC; i += blockDim.x) { sb2[i] = b2[i]; sbias[i] = bias[i]; }
    __syncthreads();

    int nid = blockIdx.x * blockDim.x + threadIdx.x;
    if (nid >= NN) return;

    const float inv = 1.0f / (float)HEADS;
    float t[2 * OC];
#pragma unroll
    for (int j = 0; j < 2 * OC; j++) t[j] = sb1[j];

    for (int c = 0; c < OC; c++) {
        float yv = g_y[nid * OC + c] * inv + sbias[c];
        yv = yv > 0.f ? yv : 0.f;
#pragma unroll
        for (int j = 0; j < 2 * OC; j++) t[j] += yv * sW1[c * (2 * OC) + j];
    }
#pragma unroll
    for (int j = 0; j < 2 * OC; j++) t[j] = t[j] > 0.f ? t[j] : 0.f;

    for (int c = 0; c < OC; c++) {
        float z = sb2[c];
#pragma unroll
        for (int j = 0; j < 2 * OC; j++) z += t[j] * sW2[j * OC + c];
        float yv = g_y[nid * OC + c] * inv + sbias[c];
        yv = yv > 0.f ? yv : 0.f;
        float rr = yv + z;
        out[nid * OC + c] = rr > 0.f ? rr : 0.f;
    }
}

// ---------------- launch -----------------------------------------------------
extern "C" void kernel_launch(void* const* d_in, const int* in_sizes, int n_in,
                              void* d_out, int out_size) {
    const float* x       = (const float*)d_in[0];
    const void*  ei      = d_in[1];
    const float* W       = (const float*)d_in[2];
    const float* att_src = (const float*)d_in[3];
    const float* att_dst = (const float*)d_in[4];
    const float* bias    = (const float*)d_in[5];
    const float* W1      = (const float*)d_in[6];
    const float* b1      = (const float*)d_in[7];
    const float* W2      = (const float*)d_in[8];
    const float* b2      = (const float*)d_in[9];
    float*       out     = (float*)d_out;

    static bool attr_done = false;
    if (!attr_done) {
        cudaFuncSetAttribute(k_gemm_mma, cudaFuncAttributeMaxDynamicSharedMemorySize,
                             SM_GEMM);
        attr_done = true;
    }

    k_detect<<<1, 32>>>((const int*)ei);
    k_init<<<(NN + 255) / 256, 256>>>();
    k_prep<<<(HC * ICC + 255) / 256, 256>>>(W);

    // CSR build
    k_hist<<<(EE + 255) / 256, 256>>>(ei);
    k_scan<<<1, 1024>>>();
    k_fill<<<(EE + 255) / 256, 256>>>(ei);

    // fused GEMM + attention logits
    dim3 ggrid((NN + BMM - 1) / BMM, HC / BNN);
    k_gemm_mma<<<ggrid, 128, SM_GEMM>>>(x, att_src, att_dst);

    // CSR aggregation (warp per dst)
    k_aggr<<<(NN + 7) / 8, 256>>>();

    // epilogue MLP
    k_mlp<<<(NN + 127) / 128, 128>>>(bias, W1, b1, W2, b2, out);
}

// round 6
// speedup vs baseline: 2.6580x; 1.3159x over previous
#include <cuda_runtime.h>
#include <cuda_bf16.h>
#include <cuda_fp16.h>
#include <cstdint>

// Problem constants (fixed shapes per reference)
#define NN    50000
#define EE    800000
#define HEADS 12
#define OC    32
#define ICC   128
#define HC    (HEADS * OC)   // 384
#define NEG_SLOPE 0.2f

#define BMM   64             // CTA M tile
#define BNN   64             // CTA N tile (= 2 heads)
#define LDA   136            // smem row stride in bf16 elems (128 + 8 pad)
#define NBLK  ((NN + 1023) / 1024)   // 49 scan blocks

// ---------------- scratch (device globals; no allocations allowed) ----------
__device__ __half2       g_h16[(size_t)NN * HC / 2]; // 38.4 MB  h (fp16)
__device__ float         g_asrc[NN * HEADS];
__device__ float         g_adst[NN * HEADS];
__device__ float         g_y[NN * OC];              // aggregated output
__device__ int           g_is64;                    // edge_index dtype flag
__device__ __nv_bfloat16 g_wt_hi[HC * ICC];         // W^T hi, [n][k]
__device__ __nv_bfloat16 g_wt_lo[HC * ICC];         // W^T lo
// CSR-by-dst structures
__device__ int g_cnt[NN];        // in-degree (real edges only)
__device__ int g_rowptr[NN];     // exclusive prefix
__device__ int g_cursor[NN];     // fill cursors
__device__ int g_csr[EE];        // src ids grouped by dst
__device__ int g_excl[NN];       // per-block exclusive scan
__device__ int g_bsum[NBLK];     // block sums

__device__ __forceinline__ void load_edge(const void* __restrict__ ei, int e,
                                          int& src, int& dst) {
    if (g_is64) {
        const long long* p = (const long long*)ei;
        src = (int)p[e];
        dst = (int)p[EE + e];
    } else {
        const int* p = (const int*)ei;
        src = p[e];
        dst = p[EE + e];
    }
}

__device__ __forceinline__ uint32_t smem_u32(const void* p) {
    uint32_t a;
    asm("{ .reg .u64 t; cvta.to.shared.u64 t, %1; cvt.u32.u64 %0, t; }" : "=r"(a) : "l"(p));
    return a;
}

// ---------------- K-1: detect edge_index dtype ------------------------------
__global__ void k_detect(const int* __restrict__ ei32) {
    if (threadIdx.x == 0 && blockIdx.x == 0) {
        bool hi_all_zero = true;
        for (int i = 0; i < 32; i++)
            if (ei32[2 * i + 1] != 0) hi_all_zero = false;
        g_is64 = hi_all_zero ? 1 : 0;
    }
}

// ---------------- K0: zero degree counters ----------------------------------
__global__ void k_init() {
    int i = blockIdx.x * blockDim.x + threadIdx.x;
    if (i < NN) g_cnt[i] = 0;
}

// ---------------- K0b: split W^T into bf16 hi/lo, [n][k] layout ------------
__global__ void k_prep(const float* __restrict__ W) {
    int i = blockIdx.x * blockDim.x + threadIdx.x;
    if (i >= HC * ICC) return;
    int n = i / ICC, k = i % ICC;
    float v = W[k * HC + n];
    __nv_bfloat16 hi = __float2bfloat16(v);
    float rem = v - __bfloat162float(hi);
    g_wt_hi[n * ICC + k] = hi;
    g_wt_lo[n * ICC + k] = __float2bfloat16(rem);
}

// ---------------- CSR build --------------------------------------------------
__global__ void k_hist(const void* __restrict__ ei) {
    int e = blockIdx.x * blockDim.x + threadIdx.x;
    if (e >= EE) return;
    int src, dst;
    load_edge(ei, e, src, dst);
    if ((unsigned)dst < NN) atomicAdd(&g_cnt[dst], 1);
}

__global__ void k_scan1() {
    __shared__ int s[1024];
    int tid = threadIdx.x;
    int idx = blockIdx.x * 1024 + tid;
    int v = (idx < NN) ? g_cnt[idx] : 0;
    s[tid] = v;
    __syncthreads();
    for (int off = 1; off < 1024; off <<= 1) {
        int t = (tid >= off) ? s[tid - off] : 0;
        __syncthreads();
        s[tid] += t;
        __syncthreads();
    }
    if (idx < NN) g_excl[idx] = s[tid] - v;
    if (tid == 1023) g_bsum[blockIdx.x] = s[1023];
}

__global__ void k_scan2() {
    if (threadIdx.x == 0) {
        int run = 0;
        for (int i = 0; i < NBLK; i++) { int t = g_bsum[i]; g_bsum[i] = run; run += t; }
    }
}

__global__ void k_scan3() {
    int idx = blockIdx.x * blockDim.x + threadIdx.x;
    if (idx < NN) {
        int r = g_excl[idx] + g_bsum[idx >> 10];
        g_rowptr[idx] = r;
        g_cursor[idx] = r;
    }
}

__global__ void k_fill(const void* __restrict__ ei) {
    int e = blockIdx.x * blockDim.x + threadIdx.x;
    if (e >= EE) return;
    int src, dst;
    load_edge(ei, e, src, dst);
    if ((unsigned)src >= NN || (unsigned)dst >= NN) return;
    int pos = atomicAdd(&g_cursor[dst], 1);
    g_csr[pos] = src;
}

// ---------------- K1: h = x @ W via mma.sync bf16 3-term, fused att logits --
#define SMB_AHI 0
#define SMB_ALO (BMM * LDA * 2)
#define SMB_BHI (2 * BMM * LDA * 2)
#define SMB_BLO (3 * BMM * LDA * 2)
#define SM_GEMM (4 * BMM * LDA * 2)

__device__ __forceinline__ void ldm_x4(uint32_t addr, uint32_t& r0, uint32_t& r1,
                                       uint32_t& r2, uint32_t& r3) {
    asm volatile("ldmatrix.sync.aligned.m8n8.x4.shared.b16 {%0,%1,%2,%3}, [%4];"
                 : "=r"(r0), "=r"(r1), "=r"(r2), "=r"(r3) : "r"(addr));
}
__device__ __forceinline__ void mma_bf16(float* d, uint32_t a0, uint32_t a1,
                                         uint32_t a2, uint32_t a3,
                                         uint32_t b0, uint32_t b1) {
    asm volatile(
        "mma.sync.aligned.m16n8k16.row.col.f32.bf16.bf16.f32 "
        "{%0,%1,%2,%3}, {%4,%5,%6,%7}, {%8,%9}, {%0,%1,%2,%3};"
        : "+f"(d[0]), "+f"(d[1]), "+f"(d[2]), "+f"(d[3])
        : "r"(a0), "r"(a1), "r"(a2), "r"(a3), "r"(b0), "r"(b1));
}

__global__ void __launch_bounds__(128) k_gemm_mma(const float* __restrict__ x,
                                                  const float* __restrict__ att_src,
                                                  const float* __restrict__ att_dst) {
    extern __shared__ char smem[];
    __nv_bfloat16* aHi = (__nv_bfloat16*)(smem + SMB_AHI);
    __nv_bfloat16* aLo = (__nv_bfloat16*)(smem + SMB_ALO);
    __nv_bfloat16* bHi = (__nv_bfloat16*)(smem + SMB_BHI);
    __nv_bfloat16* bLo = (__nv_bfloat16*)(smem + SMB_BLO);

    const int tid = threadIdx.x;
    const int wid = tid >> 5, lane = tid & 31;
    const int row0 = blockIdx.x * BMM;
    const int n0 = blockIdx.y * BNN;

#pragma unroll
    for (int j = 0; j < 16; j++) {
        int s = tid + j * 128;
        int r = s >> 5, c = (s & 31) << 2;
        float4 v = make_float4(0.f, 0.f, 0.f, 0.f);
        int grow = row0 + r;
        if (grow < NN) v = *(const float4*)(x + (size_t)grow * ICC + c);
        __nv_bfloat16 h0 = __float2bfloat16(v.x), h1 = __float2bfloat16(v.y);
        __nv_bfloat16 h2 = __float2bfloat16(v.z), h3 = __float2bfloat16(v.w);
        aHi[r * LDA + c + 0] = h0; aHi[r * LDA + c + 1] = h1;
        aHi[r * LDA + c + 2] = h2; aHi[r * LDA + c + 3] = h3;
        aLo[r * LDA + c + 0] = __float2bfloat16(v.x - __bfloat162float(h0));
        aLo[r * LDA + c + 1] = __float2bfloat16(v.y - __bfloat162float(h1));
        aLo[r * LDA + c + 2] = __float2bfloat16(v.z - __bfloat162float(h2));
        aLo[r * LDA + c + 3] = __float2bfloat16(v.w - __bfloat162float(h3));
    }
#pragma unroll
    for (int j = 0; j < 8; j++) {
        int s = tid + j * 128;
        int r = s >> 4, c = (s & 15) << 3;
        *(uint4*)(bHi + r * LDA + c) = *(const uint4*)(g_wt_hi + (n0 + r) * ICC + c);
        *(uint4*)(bLo + r * LDA + c) = *(const uint4*)(g_wt_lo + (n0 + r) * ICC + c);
    }
    __syncthreads();

    const int warpM = wid * 16;
    float acc[8][4];
#pragma unroll
    for (int nt = 0; nt < 8; nt++)
#pragma unroll
        for (int j = 0; j < 4; j++) acc[nt][j] = 0.f;

    const uint32_t aHiB = smem_u32(aHi), aLoB = smem_u32(aLo);
    const uint32_t bHiB = smem_u32(bHi), bLoB = smem_u32(bLo);
    const int arow = warpM + (lane & 15);
    const int akoff = (lane >> 4) * 8;
    // B x4 ldmatrix lane mapping: covers 16 rows x 16 k per ntp
    const int brow = ((lane >> 4) << 3) + (lane & 7);
    const int bkoff = (lane & 8);

#pragma unroll
    for (int kc = 0; kc < 8; kc++) {
        uint32_t ah0, ah1, ah2, ah3, al0, al1, al2, al3;
        uint32_t aoff = (uint32_t)((arow * LDA + kc * 16 + akoff) * 2);
        ldm_x4(aHiB + aoff, ah0, ah1, ah2, ah3);
        ldm_x4(aLoB + aoff, al0, al1, al2, al3);
#pragma unroll
        for (int ntp = 0; ntp < 4; ntp++) {
            uint32_t boff = (uint32_t)(((ntp * 16 + brow) * LDA + kc * 16 + bkoff) * 2);
            uint32_t bh0, bh1, bh2, bh3, bl0, bl1, bl2, bl3;
            ldm_x4(bHiB + boff, bh0, bh1, bh2, bh3);
            ldm_x4(bLoB + boff, bl0, bl1, bl2, bl3);
            mma_bf16(acc[2 * ntp], ah0, ah1, ah2, ah3, bh0, bh1);
            mma_bf16(acc[2 * ntp], ah0, ah1, ah2, ah3, bl0, bl1);
            mma_bf16(acc[2 * ntp], al0, al1, al2, al3, bh0, bh1);
            mma_bf16(acc[2 * ntp + 1], ah0, ah1, ah2, ah3, bh2, bh3);
            mma_bf16(acc[2 * ntp + 1], ah0, ah1, ah2, ah3, bl2, bl3);
            mma_bf16(acc[2 * ntp + 1], al0, al1, al2, al3, bh2, bh3);
        }
    }

    const int r1 = warpM + (lane >> 2);
    const int r2 = r1 + 8;
    const int grow1 = row0 + r1, grow2 = row0 + r2;
    const int cb = (lane & 3) * 2;
    const int hd0 = blockIdx.y * 2, hd1 = hd0 + 1;

    float s1h0 = 0.f, d1h0 = 0.f, s2h0 = 0.f, d2h0 = 0.f;
    float s1h1 = 0.f, d1h1 = 0.f, s2h1 = 0.f, d2h1 = 0.f;
#pragma unroll
    for (int nt = 0; nt < 8; nt++) {
        int gcol = n0 + nt * 8 + cb;
        if (grow1 < NN)
            g_h16[(size_t)grow1 * (HC / 2) + (gcol >> 1)] =
                __floats2half2_rn(acc[nt][0], acc[nt][1]);
        if (grow2 < NN)
            g_h16[(size_t)grow2 * (HC / 2) + (gcol >> 1)] =
                __floats2half2_rn(acc[nt][2], acc[nt][3]);
        float as0 = __ldg(att_src + gcol), as1 = __ldg(att_src + gcol + 1);
        float ad0 = __ldg(att_dst + gcol), ad1 = __ldg(att_dst + gcol + 1);
        if (nt < 4) {
            s1h0 += acc[nt][0] * as0 + acc[nt][1] * as1;
            d1h0 += acc[nt][0] * ad0 + acc[nt][1] * ad1;
            s2h0 += acc[nt][2] * as0 + acc[nt][3] * as1;
            d2h0 += acc[nt][2] * ad0 + acc[nt][3] * ad1;
        } else {
            s1h1 += acc[nt][0] * as0 + acc[nt][1] * as1;
            d1h1 += acc[nt][0] * ad0 + acc[nt][1] * ad1;
            s2h1 += acc[nt][2] * as0 + acc[nt][3] * as1;
            d2h1 += acc[nt][2] * ad0 + acc[nt][3] * ad1;
        }
    }
#pragma unroll
    for (int o = 1; o <= 2; o <<= 1) {
        s1h0 += __shfl_xor_sync(0xffffffffu, s1h0, o);
        d1h0 += __shfl_xor_sync(0xffffffffu, d1h0, o);
        s2h0 += __shfl_xor_sync(0xffffffffu, s2h0, o);
        d2h0 += __shfl_xor_sync(0xffffffffu, d2h0, o);
        s1h1 += __shfl_xor_sync(0xffffffffu, s1h1, o);
        d1h1 += __shfl_xor_sync(0xffffffffu, d1h1, o);
        s2h1 += __shfl_xor_sync(0xffffffffu, s2h1, o);
        d2h1 += __shfl_xor_sync(0xffffffffu, d2h1, o);
    }
    if ((lane & 3) == 0) {
        if (grow1 < NN) {
            g_asrc[grow1 * HEADS + hd0] = s1h0;
            g_adst[grow1 * HEADS + hd0] = d1h0;
            g_asrc[grow1 * HEADS + hd1] = s1h1;
            g_adst[grow1 * HEADS + hd1] = d1h1;
        }
        if (grow2 < NN) {
            g_asrc[grow2 * HEADS + hd0] = s2h0;
            g_adst[grow2 * HEADS + hd0] = d2h0;
            g_asrc[grow2 * HEADS + hd1] = s2h1;
            g_adst[grow2 * HEADS + hd1] = d2h1;
        }
    }
}

// ---------------- K5: CSR aggregation, warp per dst node -------------------
__device__ __forceinline__ float leaky(float v) {
    return v > 0.f ? v : NEG_SLOPE * v;
}

__global__ void __launch_bounds__(256) k_aggr() {
    int n = blockIdx.x * (blockDim.x >> 5) + (threadIdx.x >> 5);
    int lane = threadIdx.x & 31;
    if (n >= NN) return;

    int base = g_rowptr[n];
    int deg = g_cnt[n];

    float adst = (lane < HEADS) ? g_adst[n * HEADS + lane] : 0.f;
    float asrc_self = (lane < HEADS) ? g_asrc[n * HEADS + lane] : 0.f;

    // ---- pass 1: softmax denominator per head (lanes 0..11 = heads) ----
    float denom = (lane < HEADS) ? __expf(leaky(asrc_self + adst)) : 0.f;
    for (int i0 = 0; i0 < deg; i0 += 32) {
        int s_i = (i0 + lane < deg) ? g_csr[base + i0 + lane] : 0;
        int cnt = min(32, deg - i0);
        for (int j = 0; j < cnt; j++) {
            int src = __shfl_sync(0xffffffffu, s_i, j);
            float as = (lane < HEADS) ? g_asrc[src * HEADS + lane] : 0.f;
            if (lane < HEADS) denom += __expf(leaky(as + adst));
        }
    }
    denom += 1e-16f;

    // ---- pass 2: weighted aggregation (half2 gathers) ----
    // lane c = lane&15 owns channel pair (2c, 2c+1); p = lane>>4 picks head parity
    const int c = lane & 15, p = lane >> 4;
    float accx = 0.f, accy = 0.f;
    {   // self loop
        float al = (lane < HEADS) ? __expf(leaky(asrc_self + adst)) / denom : 0.f;
        const __half2* hr = g_h16 + (size_t)n * (HC / 2);
#pragma unroll
        for (int hp = 0; hp < 6; hp++) {
            float a = __shfl_sync(0xffffffffu, al, hp * 2 + p);
            float2 f = __half22float2(hr[(hp * 2 + p) * 16 + c]);
            accx += a * f.x;
            accy += a * f.y;
        }
    }
    for (int i0 = 0; i0 < deg; i0 += 32) {
        int s_i = (i0 + lane < deg) ? g_csr[base + i0 + lane] : 0;
        int cnt = min(32, deg - i0);
        for (int j = 0; j < cnt; j++) {
            int src = __shfl_sync(0xffffffffu, s_i, j);
            float as = (lane < HEADS) ? g_asrc[src * HEADS + lane] : 0.f;
            float al = (lane < HEADS) ? __expf(leaky(as + adst)) / denom : 0.f;
            const __half2* hr = g_h16 + (size_t)src * (HC / 2);
#pragma unroll
            for (int hp = 0; hp < 6; hp++) {
                float a = __shfl_sync(0xffffffffu, al, hp * 2 + p);
                float2 f = __half22float2(hr[(hp * 2 + p) * 16 + c]);
                accx += a * f.x;
                accy += a * f.y;
            }
        }
    }
    // combine the two head-parity halves (lane and lane^16 hold same channels)
    accx += __shfl_xor_sync(0xffffffffu, accx, 16);
    accy += __shfl_xor_sync(0xffffffffu, accy, 16);
    if (p == 0)
        *(float2*)(g_y + n * OC + 2 * c) = make_float2(accx, accy);
}

// ---------------- K6: mean + bias + relu + MLP + residual relu -------------
__global__ void k_mlp(const float* __restrict__ bias,
                      const float* __restrict__ W1, const float* __restrict__ b1,
                      const float* __restrict__ W2, const float* __restrict__ b2,
                      float* __restrict__ out) {
    __shared__ float sW1[OC * 2 * OC];
    __shared__ float sW2[2 * OC * OC];
    __shared__ float sb1[2 * OC], sb2[OC], sbias[OC];
    for (int i = threadIdx.x; i < OC * 2 * OC; i += blockDim.x) {
        sW1[i] = W1[i];
        sW2[i] = W2[i];
    }
    for (int i = threadIdx.x; i < 2 * OC; i += blockDim.x) sb1[i] = b1[i];
    for (int i = threadIdx.x; i < OC; i += blockDim.x) { sb2[i] = b2[i]; sbias[i] = bias[i]; }
    __syncthreads();

    int nid = blockIdx.x * blockDim.x + threadIdx.x;
    if (nid >= NN) return;

    const float inv = 1.0f / (float)HEADS;
    float t[2 * OC];
#pragma unroll
    for (int j = 0; j < 2 * OC; j++) t[j] = sb1[j];

    for (int cch = 0; cch < OC; cch++) {
        float yv = g_y[nid * OC + cch] * inv + sbias[cch];
        yv = yv > 0.f ? yv : 0.f;
#pragma unroll
        for (int j = 0; j < 2 * OC; j++) t[j] += yv * sW1[cch * (2 * OC) + j];
    }
#pragma unroll
    for (int j = 0; j < 2 * OC; j++) t[j] = t[j] > 0.f ? t[j] : 0.f;

    for (int cch = 0; cch < OC; cch++) {
        float z = sb2[cch];
#pragma unroll
        for (int j = 0; j < 2 * OC; j++) z += t[j] * sW2[j * OC + cch];
        float yv = g_y[nid * OC + cch] * inv + sbias[cch];
        yv = yv > 0.f ? yv : 0.f;
        float rr = yv + z;
        out[nid * OC + cch] = rr > 0.f ? rr : 0.f;
    }
}

// ---------------- launch -----------------------------------------------------
extern "C" void kernel_launch(void* const* d_in, const int* in_sizes, int n_in,
                              void* d_out, int out_size) {
    const float* x       = (const float*)d_in[0];
    const void*  ei      = d_in[1];
    const float* W       = (const float*)d_in[2];
    const float* att_src = (const float*)d_in[3];
    const float* att_dst = (const float*)d_in[4];
    const float* bias    = (const float*)d_in[5];
    const float* W1      = (const float*)d_in[6];
    const float* b1      = (const float*)d_in[7];
    const float* W2      = (const float*)d_in[8];
    const float* b2      = (const float*)d_in[9];
    float*       out     = (float*)d_out;

    static bool attr_done = false;
    if (!attr_done) {
        cudaFuncSetAttribute(k_gemm_mma, cudaFuncAttributeMaxDynamicSharedMemorySize,
                             SM_GEMM);
        attr_done = true;
    }

    k_detect<<<1, 32>>>((const int*)ei);
    k_init<<<(NN + 255) / 256, 256>>>();
    k_prep<<<(HC * ICC + 255) / 256, 256>>>(W);

    // CSR build
    k_hist<<<(EE + 255) / 256, 256>>>(ei);
    k_scan1<<<NBLK, 1024>>>();
    k_scan2<<<1, 32>>>();
    k_scan3<<<(NN + 255) / 256, 256>>>();
    k_fill<<<(EE + 255) / 256, 256>>>(ei);

    // fused GEMM + attention logits
    dim3 ggrid((NN + BMM - 1) / BMM, HC / BNN);
    k_gemm_mma<<<ggrid, 128, SM_GEMM>>>(x, att_src, att_dst);

    // CSR aggregation (warp per dst)
    k_aggr<<<(NN + 7) / 8, 256>>>();

    // epilogue MLP
    k_mlp<<<(NN + 127) / 128, 128>>>(bias, W1, b1, W2, b2, out);
}

// round 7
// speedup vs baseline: 3.2315x; 1.2158x over previous
#include <cuda_runtime.h>
#include <cuda_bf16.h>
#include <cuda_fp16.h>
#include <cstdint>

// Problem constants (fixed shapes per reference)
#define NN    50000
#define EE    800000
#define HEADS 12
#define OC    32
#define ICC   128
#define HC    (HEADS * OC)   // 384
#define NEG_SLOPE 0.2f

#define BMM   128            // CTA M tile
#define BNN   64             // CTA N tile (= 2 heads)
#define LDA   136            // smem row stride in bf16 elems (128 + 8 pad)
#define NBLK  ((NN + 1023) / 1024)   // 49 scan blocks

// ---------------- scratch (device globals; no allocations allowed) ----------
__device__ __half2       g_h16[(size_t)NN * HC / 2]; // 38.4 MB  h (fp16)
__device__ float         g_asrc[NN * HEADS];
__device__ float         g_adst[NN * HEADS];
__device__ float         g_y[NN * OC];              // aggregated output
__device__ int           g_is64;                    // edge_index dtype flag
__device__ __nv_bfloat16 g_wt_hi[HC * ICC];         // W^T hi, [n][k]
__device__ __nv_bfloat16 g_wt_lo[HC * ICC];         // W^T lo
// CSR-by-dst structures
__device__ int g_cnt[NN];        // in-degree (real edges only)
__device__ int g_rowptr[NN];     // exclusive prefix
__device__ int g_cursor[NN];     // fill cursors
__device__ int g_csr[EE];        // src ids grouped by dst
__device__ int g_excl[NN];       // per-block exclusive scan
__device__ int g_bsum[NBLK];     // block sums

__device__ __forceinline__ void load_edge(const void* __restrict__ ei, int e,
                                          int& src, int& dst) {
    if (g_is64) {
        const long long* p = (const long long*)ei;
        src = (int)p[e];
        dst = (int)p[EE + e];
    } else {
        const int* p = (const int*)ei;
        src = p[e];
        dst = p[EE + e];
    }
}

__device__ __forceinline__ uint32_t smem_u32(const void* p) {
    uint32_t a;
    asm("{ .reg .u64 t; cvta.to.shared.u64 t, %1; cvt.u32.u64 %0, t; }" : "=r"(a) : "l"(p));
    return a;
}

// ---------------- K-1: detect edge_index dtype ------------------------------
__global__ void k_detect(const int* __restrict__ ei32) {
    if (threadIdx.x == 0 && blockIdx.x == 0) {
        bool hi_all_zero = true;
        for (int i = 0; i < 32; i++)
            if (ei32[2 * i + 1] != 0) hi_all_zero = false;
        g_is64 = hi_all_zero ? 1 : 0;
    }
}

// ---------------- K0: zero degree counters ----------------------------------
__global__ void k_init() {
    int i = blockIdx.x * blockDim.x + threadIdx.x;
    if (i < NN) g_cnt[i] = 0;
}

// ---------------- K0b: split W^T into bf16 hi/lo, [n][k] layout ------------
__global__ void k_prep(const float* __restrict__ W) {
    int i = blockIdx.x * blockDim.x + threadIdx.x;
    if (i >= HC * ICC) return;
    int n = i / ICC, k = i % ICC;
    float v = W[k * HC + n];
    __nv_bfloat16 hi = __float2bfloat16(v);
    float rem = v - __bfloat162float(hi);
    g_wt_hi[n * ICC + k] = hi;
    g_wt_lo[n * ICC + k] = __float2bfloat16(rem);
}

// ---------------- CSR build --------------------------------------------------
__global__ void k_hist(const void* __restrict__ ei) {
    int e = blockIdx.x * blockDim.x + threadIdx.x;
    if (e >= EE) return;
    int src, dst;
    load_edge(ei, e, src, dst);
    if ((unsigned)dst < NN) atomicAdd(&g_cnt[dst], 1);
}

__global__ void k_scan1() {
    __shared__ int s[1024];
    int tid = threadIdx.x;
    int idx = blockIdx.x * 1024 + tid;
    int v = (idx < NN) ? g_cnt[idx] : 0;
    s[tid] = v;
    __syncthreads();
    for (int off = 1; off < 1024; off <<= 1) {
        int t = (tid >= off) ? s[tid - off] : 0;
        __syncthreads();
        s[tid] += t;
        __syncthreads();
    }
    if (idx < NN) g_excl[idx] = s[tid] - v;
    if (tid == 1023) g_bsum[blockIdx.x] = s[1023];
}

__global__ void k_scan2() {
    if (threadIdx.x == 0) {
        int run = 0;
        for (int i = 0; i < NBLK; i++) { int t = g_bsum[i]; g_bsum[i] = run; run += t; }
    }
}

__global__ void k_scan3() {
    int idx = blockIdx.x * blockDim.x + threadIdx.x;
    if (idx < NN) {
        int r = g_excl[idx] + g_bsum[idx >> 10];
        g_rowptr[idx] = r;
        g_cursor[idx] = r;
    }
}

__global__ void k_fill(const void* __restrict__ ei) {
    int e = blockIdx.x * blockDim.x + threadIdx.x;
    if (e >= EE) return;
    int src, dst;
    load_edge(ei, e, src, dst);
    if ((unsigned)src >= NN || (unsigned)dst >= NN) return;
    int pos = atomicAdd(&g_cursor[dst], 1);
    g_csr[pos] = src;
}

// ---------------- K1: h = x @ W via mma.sync bf16 3-term, fused att logits --
#define SMB_AHI 0
#define SMB_ALO (BMM * LDA * 2)
#define SMB_BHI (2 * BMM * LDA * 2)
#define SMB_BLO (SMB_BHI + BNN * LDA * 2)
#define SM_GEMM (SMB_BHI + 2 * BNN * LDA * 2)

__device__ __forceinline__ void ldm_x4(uint32_t addr, uint32_t& r0, uint32_t& r1,
                                       uint32_t& r2, uint32_t& r3) {
    asm volatile("ldmatrix.sync.aligned.m8n8.x4.shared.b16 {%0,%1,%2,%3}, [%4];"
                 : "=r"(r0), "=r"(r1), "=r"(r2), "=r"(r3) : "r"(addr));
}
__device__ __forceinline__ void mma_bf16(float* d, uint32_t a0, uint32_t a1,
                                         uint32_t a2, uint32_t a3,
                                         uint32_t b0, uint32_t b1) {
    asm volatile(
        "mma.sync.aligned.m16n8k16.row.col.f32.bf16.bf16.f32 "
        "{%0,%1,%2,%3}, {%4,%5,%6,%7}, {%8,%9}, {%0,%1,%2,%3};"
        : "+f"(d[0]), "+f"(d[1]), "+f"(d[2]), "+f"(d[3])
        : "r"(a0), "r"(a1), "r"(a2), "r"(a3), "r"(b0), "r"(b1));
}

__global__ void __launch_bounds__(256) k_gemm_mma(const float* __restrict__ x,
                                                  const float* __restrict__ att_src,
                                                  const float* __restrict__ att_dst) {
    extern __shared__ char smem[];
    __nv_bfloat16* aHi = (__nv_bfloat16*)(smem + SMB_AHI);
    __nv_bfloat16* aLo = (__nv_bfloat16*)(smem + SMB_ALO);
    __nv_bfloat16* bHi = (__nv_bfloat16*)(smem + SMB_BHI);
    __nv_bfloat16* bLo = (__nv_bfloat16*)(smem + SMB_BLO);

    const int tid = threadIdx.x;
    const int wid = tid >> 5, lane = tid & 31;
    const int row0 = blockIdx.x * BMM;
    const int n0 = blockIdx.y * BNN;

    // A tile: 128 rows x 128 fp32 -> bf16 hi/lo  (4096 float4 / 256 thr = 16)
#pragma unroll
    for (int j = 0; j < 16; j++) {
        int s = tid + j * 256;
        int r = s >> 5, c = (s & 31) << 2;
        float4 v = make_float4(0.f, 0.f, 0.f, 0.f);
        int grow = row0 + r;
        if (grow < NN) v = *(const float4*)(x + (size_t)grow * ICC + c);
        __nv_bfloat16 h0 = __float2bfloat16(v.x), h1 = __float2bfloat16(v.y);
        __nv_bfloat16 h2 = __float2bfloat16(v.z), h3 = __float2bfloat16(v.w);
        aHi[r * LDA + c + 0] = h0; aHi[r * LDA + c + 1] = h1;
        aHi[r * LDA + c + 2] = h2; aHi[r * LDA + c + 3] = h3;
        aLo[r * LDA + c + 0] = __float2bfloat16(v.x - __bfloat162float(h0));
        aLo[r * LDA + c + 1] = __float2bfloat16(v.y - __bfloat162float(h1));
        aLo[r * LDA + c + 2] = __float2bfloat16(v.z - __bfloat162float(h2));
        aLo[r * LDA + c + 3] = __float2bfloat16(v.w - __bfloat162float(h3));
    }
    // B tile: 64 rows x 128 cols (1024 uint4 / 256 thr = 4)
#pragma unroll
    for (int j = 0; j < 4; j++) {
        int s = tid + j * 256;
        int r = s >> 4, c = (s & 15) << 3;
        *(uint4*)(bHi + r * LDA + c) = *(const uint4*)(g_wt_hi + (n0 + r) * ICC + c);
        *(uint4*)(bLo + r * LDA + c) = *(const uint4*)(g_wt_lo + (n0 + r) * ICC + c);
    }
    __syncthreads();

    const int warpM = wid * 16;
    float acc[8][4];
#pragma unroll
    for (int nt = 0; nt < 8; nt++)
#pragma unroll
        for (int j = 0; j < 4; j++) acc[nt][j] = 0.f;

    const uint32_t aHiB = smem_u32(aHi), aLoB = smem_u32(aLo);
    const uint32_t bHiB = smem_u32(bHi), bLoB = smem_u32(bLo);
    const int arow = warpM + (lane & 15);
    const int akoff = (lane >> 4) * 8;
    const int brow = ((lane >> 4) << 3) + (lane & 7);
    const int bkoff = (lane & 8);

#pragma unroll
    for (int kc = 0; kc < 8; kc++) {
        uint32_t ah0, ah1, ah2, ah3, al0, al1, al2, al3;
        uint32_t aoff = (uint32_t)((arow * LDA + kc * 16 + akoff) * 2);
        ldm_x4(aHiB + aoff, ah0, ah1, ah2, ah3);
        ldm_x4(aLoB + aoff, al0, al1, al2, al3);
#pragma unroll
        for (int ntp = 0; ntp < 4; ntp++) {
            uint32_t boff = (uint32_t)(((ntp * 16 + brow) * LDA + kc * 16 + bkoff) * 2);
            uint32_t bh0, bh1, bh2, bh3, bl0, bl1, bl2, bl3;
            ldm_x4(bHiB + boff, bh0, bh1, bh2, bh3);
            ldm_x4(bLoB + boff, bl0, bl1, bl2, bl3);
            mma_bf16(acc[2 * ntp], ah0, ah1, ah2, ah3, bh0, bh1);
            mma_bf16(acc[2 * ntp], ah0, ah1, ah2, ah3, bl0, bl1);
            mma_bf16(acc[2 * ntp], al0, al1, al2, al3, bh0, bh1);
            mma_bf16(acc[2 * ntp + 1], ah0, ah1, ah2, ah3, bh2, bh3);
            mma_bf16(acc[2 * ntp + 1], ah0, ah1, ah2, ah3, bl2, bl3);
            mma_bf16(acc[2 * ntp + 1], al0, al1, al2, al3, bh2, bh3);
        }
    }

    const int r1 = warpM + (lane >> 2);
    const int r2 = r1 + 8;
    const int grow1 = row0 + r1, grow2 = row0 + r2;
    const int cb = (lane & 3) * 2;
    const int hd0 = blockIdx.y * 2, hd1 = hd0 + 1;

    float s1h0 = 0.f, d1h0 = 0.f, s2h0 = 0.f, d2h0 = 0.f;
    float s1h1 = 0.f, d1h1 = 0.f, s2h1 = 0.f, d2h1 = 0.f;
#pragma unroll
    for (int nt = 0; nt < 8; nt++) {
        int gcol = n0 + nt * 8 + cb;
        if (grow1 < NN)
            g_h16[(size_t)grow1 * (HC / 2) + (gcol >> 1)] =
                __floats2half2_rn(acc[nt][0], acc[nt][1]);
        if (grow2 < NN)
            g_h16[(size_t)grow2 * (HC / 2) + (gcol >> 1)] =
                __floats2half2_rn(acc[nt][2], acc[nt][3]);
        float as0 = __ldg(att_src + gcol), as1 = __ldg(att_src + gcol + 1);
        float ad0 = __ldg(att_dst + gcol), ad1 = __ldg(att_dst + gcol + 1);
        if (nt < 4) {
            s1h0 += acc[nt][0] * as0 + acc[nt][1] * as1;
            d1h0 += acc[nt][0] * ad0 + acc[nt][1] * ad1;
            s2h0 += acc[nt][2] * as0 + acc[nt][3] * as1;
            d2h0 += acc[nt][2] * ad0 + acc[nt][3] * ad1;
        } else {
            s1h1 += acc[nt][0] * as0 + acc[nt][1] * as1;
            d1h1 += acc[nt][0] * ad0 + acc[nt][1] * ad1;
            s2h1 += acc[nt][2] * as0 + acc[nt][3] * as1;
            d2h1 += acc[nt][2] * ad0 + acc[nt][3] * ad1;
        }
    }
#pragma unroll
    for (int o = 1; o <= 2; o <<= 1) {
        s1h0 += __shfl_xor_sync(0xffffffffu, s1h0, o);
        d1h0 += __shfl_xor_sync(0xffffffffu, d1h0, o);
        s2h0 += __shfl_xor_sync(0xffffffffu, s2h0, o);
        d2h0 += __shfl_xor_sync(0xffffffffu, d2h0, o);
        s1h1 += __shfl_xor_sync(0xffffffffu, s1h1, o);
        d1h1 += __shfl_xor_sync(0xffffffffu, d1h1, o);
        s2h1 += __shfl_xor_sync(0xffffffffu, s2h1, o);
        d2h1 += __shfl_xor_sync(0xffffffffu, d2h1, o);
    }
    if ((lane & 3) == 0) {
        if (grow1 < NN) {
            g_asrc[grow1 * HEADS + hd0] = s1h0;
            g_adst[grow1 * HEADS + hd0] = d1h0;
            g_asrc[grow1 * HEADS + hd1] = s1h1;
            g_adst[grow1 * HEADS + hd1] = d1h1;
        }
        if (grow2 < NN) {
            g_asrc[grow2 * HEADS + hd0] = s2h0;
            g_adst[grow2 * HEADS + hd0] = d2h0;
            g_asrc[grow2 * HEADS + hd1] = s2h1;
            g_adst[grow2 * HEADS + hd1] = d2h1;
        }
    }
}

// ---------------- K5: single-pass CSR aggregation, warp per dst node -------
__device__ __forceinline__ float leaky(float v) {
    return v > 0.f ? v : NEG_SLOPE * v;
}

__global__ void __launch_bounds__(256) k_aggr() {
    int n = blockIdx.x * (blockDim.x >> 5) + (threadIdx.x >> 5);
    int lane = threadIdx.x & 31;
    if (n >= NN) return;

    const int base = g_rowptr[n];
    const int deg = g_cnt[n];
    const int c = lane & 15, p = lane >> 4;   // channel pair, head parity

    const float adst = (lane < HEADS) ? g_adst[n * HEADS + lane] : 0.f;

    // per-head unnormalized accumulators: head hp*2+p, channels (2c, 2c+1)
    float accx[6], accy[6];
#pragma unroll
    for (int hp = 0; hp < 6; hp++) { accx[hp] = 0.f; accy[hp] = 0.f; }
    float denom;

    {   // self loop
        float ex = (lane < HEADS)
                   ? __expf(leaky(g_asrc[n * HEADS + lane] + adst)) : 0.f;
        denom = ex;
        const __half2* hr = g_h16 + (size_t)n * (HC / 2);
#pragma unroll
        for (int hp = 0; hp < 6; hp++) {
            float a = __shfl_sync(0xffffffffu, ex, hp * 2 + p);
            float2 f = __half22float2(hr[(hp * 2 + p) * 16 + c]);
            accx[hp] += a * f.x;
            accy[hp] += a * f.y;
        }
    }
    for (int i0 = 0; i0 < deg; i0 += 32) {
        int s_i = (i0 + lane < deg) ? g_csr[base + i0 + lane] : 0;
        int cnt = min(32, deg - i0);
        for (int j = 0; j < cnt; j++) {
            int src = __shfl_sync(0xffffffffu, s_i, j);
            float ex = (lane < HEADS)
                       ? __expf(leaky(g_asrc[src * HEADS + lane] + adst)) : 0.f;
            denom += ex;
            const __half2* hr = g_h16 + (size_t)src * (HC / 2);
#pragma unroll
            for (int hp = 0; hp < 6; hp++) {
                float a = __shfl_sync(0xffffffffu, ex, hp * 2 + p);
                float2 f = __half22float2(hr[(hp * 2 + p) * 16 + c]);
                accx[hp] += a * f.x;
                accy[hp] += a * f.y;
            }
        }
    }

    // normalize per head and sum heads
    float resx = 0.f, resy = 0.f;
#pragma unroll
    for (int hp = 0; hp < 6; hp++) {
        float dh = __shfl_sync(0xffffffffu, denom, hp * 2 + p) + 1e-16f;
        float rinv = __frcp_rn(dh);
        resx += accx[hp] * rinv;
        resy += accy[hp] * rinv;
    }
    resx += __shfl_xor_sync(0xffffffffu, resx, 16);
    resy += __shfl_xor_sync(0xffffffffu, resy, 16);
    if (p == 0)
        *(float2*)(g_y + n * OC + 2 * c) = make_float2(resx, resy);
}

// ---------------- K6: mean + bias + relu + MLP + residual relu -------------
__global__ void k_mlp(const float* __restrict__ bias,
                      const float* __restrict__ W1, const float* __restrict__ b1,
                      const float* __restrict__ W2, const float* __restrict__ b2,
                      float* __restrict__ out) {
    __shared__ float sW1[OC * 2 * OC];
    __shared__ float sW2[2 * OC * OC];
    __shared__ float sb1[2 * OC], sb2[OC], sbias[OC];
    for (int i = threadIdx.x; i < OC * 2 * OC; i += blockDim.x) {
        sW1[i] = W1[i];
        sW2[i] = W2[i];
    }
    for (int i = threadIdx.x; i < 2 * OC; i += blockDim.x) sb1[i] = b1[i];
    for (int i = threadIdx.x; i < OC; i += blockDim.x) { sb2[i] = b2[i]; sbias[i] = bias[i]; }
    __syncthreads();

    int nid = blockIdx.x * blockDim.x + threadIdx.x;
    if (nid >= NN) return;

    const float inv = 1.0f / (float)HEADS;
    float t[2 * OC];
#pragma unroll
    for (int j = 0; j < 2 * OC; j++) t[j] = sb1[j];

    for (int cch = 0; cch < OC; cch++) {
        float yv = g_y[nid * OC + cch] * inv + sbias[cch];
        yv = yv > 0.f ? yv : 0.f;
#pragma unroll
        for (int j = 0; j < 2 * OC; j++) t[j] += yv * sW1[cch * (2 * OC) + j];
    }
#pragma unroll
    for (int j = 0; j < 2 * OC; j++) t[j] = t[j] > 0.f ? t[j] : 0.f;

    for (int cch = 0; cch < OC; cch++) {
        float z = sb2[cch];
#pragma unroll
        for (int j = 0; j < 2 * OC; j++) z += t[j] * sW2[j * OC + cch];
        float yv = g_y[nid * OC + cch] * inv + sbias[cch];
        yv = yv > 0.f ? yv : 0.f;
        float rr = yv + z;
        out[nid * OC + cch] = rr > 0.f ? rr : 0.f;
    }
}

// ---------------- launch -----------------------------------------------------
extern "C" void kernel_launch(void* const* d_in, const int* in_sizes, int n_in,
                              void* d_out, int out_size) {
    const float* x       = (const float*)d_in[0];
    const void*  ei      = d_in[1];
    const float* W       = (const float*)d_in[2];
    const float* att_src = (const float*)d_in[3];
    const float* att_dst = (const float*)d_in[4];
    const float* bias    = (const float*)d_in[5];
    const float* W1      = (const float*)d_in[6];
    const float* b1      = (const float*)d_in[7];
    const float* W2      = (const float*)d_in[8];
    const float* b2      = (const float*)d_in[9];
    float*       out     = (float*)d_out;

    static bool attr_done = false;
    if (!attr_done) {
        cudaFuncSetAttribute(k_gemm_mma, cudaFuncAttributeMaxDynamicSharedMemorySize,
                             SM_GEMM);
        attr_done = true;
    }

    k_detect<<<1, 32>>>((const int*)ei);
    k_init<<<(NN + 255) / 256, 256>>>();
    k_prep<<<(HC * ICC + 255) / 256, 256>>>(W);

    // CSR build
    k_hist<<<(EE + 255) / 256, 256>>>(ei);
    k_scan1<<<NBLK, 1024>>>();
    k_scan2<<<1, 32>>>();
    k_scan3<<<(NN + 255) / 256, 256>>>();
    k_fill<<<(EE + 255) / 256, 256>>>(ei);

    // fused GEMM + attention logits
    dim3 ggrid((NN + BMM - 1) / BMM, HC / BNN);
    k_gemm_mma<<<ggrid, 256, SM_GEMM>>>(x, att_src, att_dst);

    // single-pass CSR aggregation (warp per dst)
    k_aggr<<<(NN + 7) / 8, 256>>>();

    // epilogue MLP
    k_mlp<<<(NN + 127) / 128, 128>>>(bias, W1, b1, W2, b2, out);
}